// round 4
// baseline (speedup 1.0000x reference)
#include <cuda_runtime.h>
#include <cuda_bf16.h>
#include <math.h>

#define N_NODES 100000
#define N_EDGES 800000
#define D 64
#define D_FEAT 10
#define VOCAB 100
#define EPS 1e-8f

// packed fp32x2 FMA (sm_100+; ptxas only emits via explicit PTX)
#define FMA_F32X2(out, a, b, c) \
    asm("fma.rn.f32x2 %0, %1, %2, %3;" : "=l"(out) : "l"(a), "l"(b), "l"(c))
#define ADD_F32X2(out, a, b) \
    asm("add.rn.f32x2 %0, %1, %2;" : "=l"(out) : "l"(a), "l"(b))

// ---------------- static device scratch ----------------
__device__ float g_z[N_NODES * D];      // z1 (layer-1 pre-aggregation linear output)
__device__ float g_z2[N_NODES * D];     // z2 (layer-2 linear output)
__device__ int   g_indeg[N_NODES];
__device__ int   g_off[N_NODES + 1];
__device__ int   g_cursor[N_NODES];
__device__ int   g_srcs[N_EDGES];
__device__ float g_nv[VOCAB * D];       // node_emb @ conv1_W^T
__device__ float g_fw2t[D_FEAT * D];    // (conv1_W @ feat_W) transposed [k][d]
__device__ float g_c[D];                // conv1_W @ feat_b

// ---------------- CSR build ----------------
__global__ void count_kernel(const int2* __restrict__ edges) {
    int e = blockIdx.x * blockDim.x + threadIdx.x;
    if (e < N_EDGES) atomicAdd(&g_indeg[edges[e].y], 1);
}

#define SCAN_T 1024
#define SCAN_CHUNK ((N_NODES + SCAN_T - 1) / SCAN_T)  // 98

__global__ void scan_kernel() {
    __shared__ int warp_sums[32];
    int tid  = threadIdx.x;
    int lane = tid & 31;
    int wid  = tid >> 5;

    int start = tid * SCAN_CHUNK;
    int end   = min(start + SCAN_CHUNK, N_NODES);

    int total = 0;
    for (int i = start; i < end; i++) total += g_indeg[i];

    int v = total;
    #pragma unroll
    for (int o = 1; o < 32; o <<= 1) {
        int n = __shfl_up_sync(0xFFFFFFFFu, v, o);
        if (lane >= o) v += n;
    }
    if (lane == 31) warp_sums[wid] = v;
    __syncthreads();
    if (wid == 0) {
        int w = warp_sums[lane];
        #pragma unroll
        for (int o = 1; o < 32; o <<= 1) {
            int n = __shfl_up_sync(0xFFFFFFFFu, w, o);
            if (lane >= o) w += n;
        }
        warp_sums[lane] = w;
    }
    __syncthreads();

    int excl = v - total + (wid > 0 ? warp_sums[wid - 1] : 0);

    int run = excl;
    for (int i = start; i < end; i++) {
        int c = g_indeg[i];
        g_off[i]    = run;
        g_cursor[i] = run;
        run += c;
    }
    if (tid == SCAN_T - 1) g_off[N_NODES] = run;
}

__global__ void place_kernel(const int2* __restrict__ edges) {
    int e = blockIdx.x * blockDim.x + threadIdx.x;
    if (e < N_EDGES) {
        int2 ed = edges[e];
        int slot = atomicAdd(&g_cursor[ed.y], 1);
        g_srcs[slot] = ed.x;
    }
}

// ---------------- precompute folded weights ----------------
__global__ void precompute_kernel(const float* __restrict__ node_emb,
                                  const float* __restrict__ feat_W,
                                  const float* __restrict__ feat_b,
                                  const float* __restrict__ W) {
    int d = threadIdx.x;  // 0..63
    if (blockIdx.x == 0) {
        float wrow[D];
        #pragma unroll
        for (int j = 0; j < D; j++) wrow[j] = W[d * D + j];
        #pragma unroll
        for (int k = 0; k < D_FEAT; k++) {
            float s = 0.f;
            #pragma unroll
            for (int j = 0; j < D; j++) s += wrow[j] * feat_W[j * D_FEAT + k];
            g_fw2t[k * D + d] = s;
        }
        float cb = 0.f;
        #pragma unroll
        for (int j = 0; j < D; j++) cb += wrow[j] * feat_b[j];
        g_c[d] = cb;
    } else {
        int v = blockIdx.x - 1;
        __shared__ float se[D];
        se[d] = node_emb[v * D + d];
        __syncthreads();
        float s = 0.f;
        #pragma unroll
        for (int j = 0; j < D; j++) s += W[d * D + j] * se[j];
        g_nv[v * D + d] = s;
    }
}

// ---------------- z1 = nv[nodes] + features @ fw2^T + c ----------------
__global__ __launch_bounds__(256)
void z1_kernel(const int* __restrict__ nodes, const float* __restrict__ features) {
    __shared__ float s_fw2t[D_FEAT * D];
    __shared__ float s_c[D];
    int tid = threadIdx.x;
    for (int i = tid; i < D_FEAT * D; i += 256) s_fw2t[i] = g_fw2t[i];
    if (tid < D) s_c[tid] = g_c[tid];
    __syncthreads();

    int q    = blockIdx.x * 256 + tid;   // quad id
    int node = q >> 4;
    int dq   = (q & 15) * 4;

    int tok = __ldg(&nodes[node]);
    const float* f = features + node * D_FEAT;
    float fk[D_FEAT];
    #pragma unroll
    for (int k = 0; k < D_FEAT; k++) fk[k] = f[k];

    float4 acc = *(const float4*)&g_nv[tok * D + dq];
    float4 cc  = *(const float4*)&s_c[dq];
    acc.x += cc.x; acc.y += cc.y; acc.z += cc.z; acc.w += cc.w;

    #pragma unroll
    for (int k = 0; k < D_FEAT; k++) {
        float4 w4 = *(const float4*)&s_fw2t[k * D + dq];
        acc.x += fk[k] * w4.x; acc.y += fk[k] * w4.y;
        acc.z += fk[k] * w4.z; acc.w += fk[k] * w4.w;
    }
    *(float4*)&g_z[node * D + dq] = acc;
}

// ---------------- MLP-8 warp aggregation helper ----------------
// acc(lane) = z[node][2*lane..2*lane+1] + sum_{neighbors a} z[a][...]
__device__ __forceinline__ float2 agg_node(const float* __restrict__ z,
                                           int node, int lane) {
    unsigned long long acc =
        *(const unsigned long long*)&z[node * D + lane * 2];
    int s0 = __ldg(&g_off[node]);
    int s1 = __ldg(&g_off[node + 1]);

    for (int base = s0; base < s1; base += 8) {
        int t  = base + (lane & 7);
        int my = (t < s1) ? __ldg(&g_srcs[t]) : 0;
        int cnt = s1 - base;  // >=1; effective batch = min(8, cnt)

        unsigned long long v[8];
        #pragma unroll
        for (int k = 0; k < 8; k++) {
            int a = __shfl_sync(0xFFFFFFFFu, my, k);
            v[k] = (k < cnt)
                 ? *(const unsigned long long*)&z[a * D + lane * 2]
                 : 0ULL;
        }
        #pragma unroll
        for (int k = 0; k < 8; k++) ADD_F32X2(acc, acc, v[k]);
    }
    float2 r;
    asm("mov.b64 {%0, %1}, %2;" : "=f"(r.x), "=f"(r.y) : "l"(acc));
    return r;
}

// ---------------- fused layer: z2 = relu(z1 + A z1 + b) @ W^T ----------------
// Persistent. Phase 1: 8 warps aggregate 8 nodes -> h rows in smem.
// Phase 2: 4 teams of 64 threads GEMV the 8 rows with packed f32x2 FMA.
#define FUSE_GRID 296
__global__ __launch_bounds__(256, 2)
void fused_layer_kernel(const float* __restrict__ zin, float* __restrict__ zout,
                        const float* __restrict__ W, const float* __restrict__ bvec) {
    __shared__ __align__(16) float xs[8][D];

    int tid  = threadIdx.x;
    int warp = tid >> 5;
    int lane = tid & 31;
    int sub  = tid >> 6;   // gemm team
    int t    = tid & 63;   // output dim

    // W row for output t as packed pairs (loop-invariant, lives in regs)
    unsigned long long w2[32];
    const unsigned long long* Wp = (const unsigned long long*)(W + t * D);
    #pragma unroll
    for (int k = 0; k < 32; k++) w2[k] = Wp[k];

    float2 b2 = *(const float2*)&bvec[lane * 2];

    for (int base = blockIdx.x * 8; base < N_NODES; base += FUSE_GRID * 8) {
        // phase 1: aggregate + bias + relu -> smem
        int node = base + warp;
        float2 acc = agg_node(zin, node, lane);
        acc.x = fmaxf(acc.x + b2.x, 0.f);
        acc.y = fmaxf(acc.y + b2.y, 0.f);
        *(float2*)&xs[warp][lane * 2] = acc;
        __syncthreads();

        // phase 2: z2 rows for nodes 2*sub, 2*sub+1
        const unsigned long long* x0 = (const unsigned long long*)xs[2 * sub];
        const unsigned long long* x1 = (const unsigned long long*)xs[2 * sub + 1];
        unsigned long long a0 = 0ULL, a1 = 0ULL, c0 = 0ULL, c1 = 0ULL;
        #pragma unroll
        for (int d = 0; d < 32; d += 2) {
            FMA_F32X2(a0, x0[d],     w2[d],     a0);
            FMA_F32X2(a1, x0[d + 1], w2[d + 1], a1);
            FMA_F32X2(c0, x1[d],     w2[d],     c0);
            FMA_F32X2(c1, x1[d + 1], w2[d + 1], c1);
        }
        float a0x, a0y, a1x, a1y, c0x, c0y, c1x, c1y;
        asm("mov.b64 {%0, %1}, %2;" : "=f"(a0x), "=f"(a0y) : "l"(a0));
        asm("mov.b64 {%0, %1}, %2;" : "=f"(a1x), "=f"(a1y) : "l"(a1));
        asm("mov.b64 {%0, %1}, %2;" : "=f"(c0x), "=f"(c0y) : "l"(c0));
        asm("mov.b64 {%0, %1}, %2;" : "=f"(c1x), "=f"(c1y) : "l"(c1));
        zout[(base + 2 * sub)     * D + t] = (a0x + a0y) + (a1x + a1y);
        zout[(base + 2 * sub + 1) * D + t] = (c0x + c0y) + (c1x + c1y);
        __syncthreads();
    }
}

// ---------------- fused final: agg + bias + relu + cosine ----------------
__global__ __launch_bounds__(256)
void agg_cos_kernel(const float* __restrict__ z,
                    const float* __restrict__ bvec,
                    const float* __restrict__ pattern_emb,
                    const int* __restrict__ pid,
                    float* __restrict__ out) {
    int node = blockIdx.x * 8 + (threadIdx.x >> 5);
    int lane = threadIdx.x & 31;

    float2 acc = agg_node(z, node, lane);
    float2 b2 = *(const float2*)&bvec[lane * 2];
    acc.x = fmaxf(acc.x + b2.x, 0.f);
    acc.y = fmaxf(acc.y + b2.y, 0.f);

    int p_id = __ldg(pid);
    float2 pv = *(const float2*)&pattern_emb[p_id * D + lane * 2];

    float num = acc.x * pv.x + acc.y * pv.y;
    float sq  = acc.x * acc.x + acc.y * acc.y;
    float psq = pv.x * pv.x + pv.y * pv.y;

    #pragma unroll
    for (int o = 16; o > 0; o >>= 1) {
        num += __shfl_xor_sync(0xFFFFFFFFu, num, o);
        sq  += __shfl_xor_sync(0xFFFFFFFFu, sq, o);
        psq += __shfl_xor_sync(0xFFFFFFFFu, psq, o);
    }
    if (lane == 0) {
        float denom = fmaxf(sqrtf(sq), EPS) * fmaxf(sqrtf(psq), EPS);
        out[node] = num / denom;
    }
}

// ---------------- launch ----------------
extern "C" void kernel_launch(void* const* d_in, const int* in_sizes, int n_in,
                              void* d_out, int out_size) {
    const int*   nodes       = (const int*)d_in[0];
    const int2*  edges       = (const int2*)d_in[1];
    const float* features    = (const float*)d_in[2];
    const float* node_emb    = (const float*)d_in[3];
    const float* feat_W      = (const float*)d_in[4];
    const float* feat_b      = (const float*)d_in[5];
    const float* conv1_W     = (const float*)d_in[6];
    const float* conv1_b     = (const float*)d_in[7];
    const float* pattern_emb = (const float*)d_in[8];
    const int*   pattern_id  = (const int*)d_in[9];
    float*       out         = (float*)d_out;

    float* z; float* z2; int* indeg;
    cudaGetSymbolAddress((void**)&z,     g_z);
    cudaGetSymbolAddress((void**)&z2,    g_z2);
    cudaGetSymbolAddress((void**)&indeg, g_indeg);

    // CSR build
    cudaMemsetAsync(indeg, 0, N_NODES * sizeof(int));
    count_kernel<<<(N_EDGES + 255) / 256, 256>>>(edges);
    scan_kernel<<<1, SCAN_T>>>();
    place_kernel<<<(N_EDGES + 255) / 256, 256>>>(edges);

    // folded weights + z1
    precompute_kernel<<<VOCAB + 1, D>>>(node_emb, feat_W, feat_b, conv1_W);
    z1_kernel<<<(N_NODES * 16) / 256, 256>>>(nodes, features);

    // layer 1 agg + relu + layer 2 linear, fused (h never hits memory)
    fused_layer_kernel<<<FUSE_GRID, 256>>>(z, z2, conv1_W, conv1_b);

    // layer 2 agg + relu + cosine
    agg_cos_kernel<<<N_NODES / 8, 256>>>(z2, conv1_b, pattern_emb, pattern_id, out);
}